// round 2
// baseline (speedup 1.0000x reference)
#include <cuda_runtime.h>
#include <math.h>

#define NN   50000
#define BB   50
#define NPGc 1000
#define EE   300000
#define HH   256
#define KSEL 500

// ---------------- scratch (static device globals; no allocation) ----------------
__device__ float d_h1[NN * HH];      // layer1 output
__device__ float d_g [NN * HH];      // aggregated h1 (pre-GEMM)
__device__ float d_h [NN * HH];      // layer2 output
__device__ int   d_indeg[NN];
__device__ int   d_rowptr[NN + 1];
__device__ int   d_fill[NN];
__device__ int   d_col[EE];          // CSR: src node per incoming edge, grouped by dst
__device__ float d_dinv[NN];
__device__ float d_r[NN];
__device__ float d_root[NN];
__device__ float d_score[NN];

// ---------------- helpers ----------------
__device__ __forceinline__ unsigned tf32r(float f) {
    unsigned u;
    asm("cvt.rna.tf32.f32 %0, %1;" : "=r"(u) : "f"(f));
    return u;
}

// ---------------- CSR build ----------------
__global__ void k_zero() {
    int i = blockIdx.x * blockDim.x + threadIdx.x;
    if (i < NN) { d_indeg[i] = 0; d_fill[i] = 0; d_r[i] = 0.f; d_root[i] = 0.f; }
}

__global__ void k_hist(const int* __restrict__ dst) {
    int i = blockIdx.x * blockDim.x + threadIdx.x;
    if (i < EE) atomicAdd(&d_indeg[dst[i]], 1);
}

// single-block exclusive scan (shuffle-based)
__global__ void k_scan() {
    __shared__ int wsum[32];
    __shared__ int carry;
    int t = threadIdx.x, lane = t & 31, wid = t >> 5;
    if (t == 0) carry = 0;
    __syncthreads();
    for (int base = 0; base < NN; base += 1024) {
        int i = base + t;
        int v = (i < NN) ? d_indeg[i] : 0;
        int sv = v;
        #pragma unroll
        for (int off = 1; off < 32; off <<= 1) {
            int n = __shfl_up_sync(0xffffffffu, sv, off);
            if (lane >= off) sv += n;
        }
        if (lane == 31) wsum[wid] = sv;
        __syncthreads();
        if (wid == 0) {
            int w = wsum[lane];
            #pragma unroll
            for (int off = 1; off < 32; off <<= 1) {
                int n = __shfl_up_sync(0xffffffffu, w, off);
                if (lane >= off) w += n;
            }
            wsum[lane] = w;
        }
        __syncthreads();
        int incl = sv + (wid > 0 ? wsum[wid - 1] : 0);
        if (i < NN) {
            d_rowptr[i] = carry + incl - v;            // exclusive
            d_dinv[i]   = rsqrtf((float)(v + 1));      // deg = indeg + self-loop
        }
        int total = wsum[31];
        __syncthreads();
        if (t == 0) carry += total;
        __syncthreads();
    }
    if (t == 0) d_rowptr[NN] = carry;
}

__global__ void k_scatter(const int* __restrict__ src, const int* __restrict__ dst) {
    int i = blockIdx.x * blockDim.x + threadIdx.x;
    if (i < EE) {
        int d = dst[i];
        int p = d_rowptr[d] + atomicAdd(&d_fill[d], 1);
        d_col[p] = src[i];
    }
}

// ---------------- layer 1: fused onehot-gather GCN conv (warp per node) ----------------
__global__ __launch_bounds__(256) void k_layer1(const int* __restrict__ x,
                                                const float* __restrict__ W1,
                                                const float* __restrict__ b1) {
    int node = (blockIdx.x * blockDim.x + threadIdx.x) >> 5;
    int lane = threadIdx.x & 31;
    if (node >= NN) return;
    float dd = d_dinv[node];
    float4 a0, a1;
    {
        const float4* p = (const float4*)(W1 + (size_t)x[node] * HH) + lane * 2;
        float4 v0 = p[0], v1 = p[1];
        a0.x = dd * v0.x; a0.y = dd * v0.y; a0.z = dd * v0.z; a0.w = dd * v0.w;
        a1.x = dd * v1.x; a1.y = dd * v1.y; a1.z = dd * v1.z; a1.w = dd * v1.w;
    }
    int beg = d_rowptr[node], end = d_rowptr[node + 1];
    for (int e = beg; e < end; e++) {
        int s = d_col[e];
        float w = d_dinv[s];
        const float4* p = (const float4*)(W1 + (size_t)x[s] * HH) + lane * 2;
        float4 v0 = p[0], v1 = p[1];
        a0.x += w * v0.x; a0.y += w * v0.y; a0.z += w * v0.z; a0.w += w * v0.w;
        a1.x += w * v1.x; a1.y += w * v1.y; a1.z += w * v1.z; a1.w += w * v1.w;
    }
    const float4* b4 = (const float4*)b1 + lane * 2;
    float4 c0 = b4[0], c1 = b4[1];
    float4 o0, o1;
    o0.x = fmaxf(dd * a0.x + c0.x, 0.f); o0.y = fmaxf(dd * a0.y + c0.y, 0.f);
    o0.z = fmaxf(dd * a0.z + c0.z, 0.f); o0.w = fmaxf(dd * a0.w + c0.w, 0.f);
    o1.x = fmaxf(dd * a1.x + c1.x, 0.f); o1.y = fmaxf(dd * a1.y + c1.y, 0.f);
    o1.z = fmaxf(dd * a1.z + c1.z, 0.f); o1.w = fmaxf(dd * a1.w + c1.w, 0.f);
    float4* outp = (float4*)(d_h1 + (size_t)node * HH) + lane * 2;
    outp[0] = o0; outp[1] = o1;
}

// ---------------- layer 2 aggregation (A-hat * h1), warp per node ----------------
__global__ __launch_bounds__(256) void k_agg() {
    int node = (blockIdx.x * blockDim.x + threadIdx.x) >> 5;
    int lane = threadIdx.x & 31;
    if (node >= NN) return;
    float dd = d_dinv[node];
    float4 a0, a1;
    {
        const float4* p = (const float4*)(d_h1 + (size_t)node * HH) + lane * 2;
        float4 v0 = p[0], v1 = p[1];
        a0.x = dd * v0.x; a0.y = dd * v0.y; a0.z = dd * v0.z; a0.w = dd * v0.w;
        a1.x = dd * v1.x; a1.y = dd * v1.y; a1.z = dd * v1.z; a1.w = dd * v1.w;
    }
    int beg = d_rowptr[node], end = d_rowptr[node + 1];
    for (int e = beg; e < end; e++) {
        int s = d_col[e];
        float w = d_dinv[s];
        const float4* p = (const float4*)(d_h1 + (size_t)s * HH) + lane * 2;
        float4 v0 = p[0], v1 = p[1];
        a0.x += w * v0.x; a0.y += w * v0.y; a0.z += w * v0.z; a0.w += w * v0.w;
        a1.x += w * v1.x; a1.y += w * v1.y; a1.z += w * v1.z; a1.w += w * v1.w;
    }
    float4 o0, o1;
    o0.x = dd * a0.x; o0.y = dd * a0.y; o0.z = dd * a0.z; o0.w = dd * a0.w;
    o1.x = dd * a1.x; o1.y = dd * a1.y; o1.z = dd * a1.z; o1.w = dd * a1.w;
    float4* outp = (float4*)(d_g + (size_t)node * HH) + lane * 2;
    outp[0] = o0; outp[1] = o1;
}

// ---------------- GEMM: h = relu(d_g @ W2 + b2) via TF32 tensor cores ----------------
// Block tile 128x128, BK=32, 8 warps (2x4), warp tile 64x32 via m16n8k8.
// Epilogue fuses r = h.Wrel and root = h.Wroot (shfl reduce + atomicAdd).
#define BM 128
#define BN 128
#define BK 32
#define SPAD 132   // smem row stride (floats), pad 4 to kill k-conflicts

__global__ __launch_bounds__(256) void k_gemm(const float* __restrict__ W2,
                                              const float* __restrict__ b2,
                                              const float* __restrict__ Wrel,
                                              const float* __restrict__ Wroot) {
    __shared__ __align__(16) float As[BK][SPAD];   // tf32 bits, [k][m]
    __shared__ __align__(16) float Bs[BK][SPAD];   // tf32 bits, [k][n]

    int tid = threadIdx.x;
    int lane = tid & 31;
    int warpId = tid >> 5;
    int warp_m = warpId & 1;       // 0..1
    int warp_n = warpId >> 1;      // 0..3
    int rowBase = blockIdx.x * BM;
    int colBase = blockIdx.y * BN;

    float c[4][4][4];
    #pragma unroll
    for (int mt = 0; mt < 4; mt++)
        #pragma unroll
        for (int nt = 0; nt < 4; nt++)
            #pragma unroll
            for (int q = 0; q < 4; q++) c[mt][nt][q] = 0.f;

    for (int k0 = 0; k0 < HH; k0 += BK) {
        // load A tile: 128 rows x 32 k (8 float4 per row), 1024 float4 / 256 thr
        #pragma unroll
        for (int i = 0; i < 4; i++) {
            int idx = tid + i * 256;
            int row = idx >> 3, cq = idx & 7;
            int gr = rowBase + row;
            float4 v = make_float4(0.f, 0.f, 0.f, 0.f);
            if (gr < NN) v = *(const float4*)(d_g + (size_t)gr * HH + k0 + cq * 4);
            As[cq * 4 + 0][row] = __uint_as_float(tf32r(v.x));
            As[cq * 4 + 1][row] = __uint_as_float(tf32r(v.y));
            As[cq * 4 + 2][row] = __uint_as_float(tf32r(v.z));
            As[cq * 4 + 3][row] = __uint_as_float(tf32r(v.w));
        }
        // load B tile: 32 k-rows x 128 n (32 float4 per row)
        #pragma unroll
        for (int i = 0; i < 4; i++) {
            int idx = tid + i * 256;
            int row = idx >> 5, cq = idx & 31;
            float4 v = *(const float4*)(W2 + (size_t)(k0 + row) * HH + colBase + cq * 4);
            float4 t;
            t.x = __uint_as_float(tf32r(v.x));
            t.y = __uint_as_float(tf32r(v.y));
            t.z = __uint_as_float(tf32r(v.z));
            t.w = __uint_as_float(tf32r(v.w));
            *(float4*)&Bs[row][cq * 4] = t;
        }
        __syncthreads();

        #pragma unroll
        for (int ks = 0; ks < 4; ks++) {
            int kb = ks * 8;
            int kc = lane & 3;
            int gr = lane >> 2;
            unsigned a[4][4];
            #pragma unroll
            for (int mt = 0; mt < 4; mt++) {
                int mb = warp_m * 64 + mt * 16;
                a[mt][0] = __float_as_uint(As[kb + kc    ][mb + gr    ]);
                a[mt][1] = __float_as_uint(As[kb + kc    ][mb + gr + 8]);
                a[mt][2] = __float_as_uint(As[kb + kc + 4][mb + gr    ]);
                a[mt][3] = __float_as_uint(As[kb + kc + 4][mb + gr + 8]);
            }
            unsigned bfr[4][2];
            #pragma unroll
            for (int nt = 0; nt < 4; nt++) {
                int nb = warp_n * 32 + nt * 8;
                bfr[nt][0] = __float_as_uint(Bs[kb + kc    ][nb + gr]);
                bfr[nt][1] = __float_as_uint(Bs[kb + kc + 4][nb + gr]);
            }
            #pragma unroll
            for (int mt = 0; mt < 4; mt++)
                #pragma unroll
                for (int nt = 0; nt < 4; nt++) {
                    asm volatile(
                        "mma.sync.aligned.m16n8k8.row.col.f32.tf32.tf32.f32 "
                        "{%0,%1,%2,%3}, {%4,%5,%6,%7}, {%8,%9}, {%0,%1,%2,%3};"
                        : "+f"(c[mt][nt][0]), "+f"(c[mt][nt][1]),
                          "+f"(c[mt][nt][2]), "+f"(c[mt][nt][3])
                        : "r"(a[mt][0]), "r"(a[mt][1]), "r"(a[mt][2]), "r"(a[mt][3]),
                          "r"(bfr[nt][0]), "r"(bfr[nt][1]));
                }
        }
        __syncthreads();
    }

    // epilogue: bias + relu + store h, fused r/root partial dot products
    #pragma unroll
    for (int mt = 0; mt < 4; mt++) {
        int r0 = rowBase + warp_m * 64 + mt * 16 + (lane >> 2);
        int r1 = r0 + 8;
        float pr0 = 0.f, po0 = 0.f, pr1 = 0.f, po1 = 0.f;
        #pragma unroll
        for (int nt = 0; nt < 4; nt++) {
            int col = colBase + warp_n * 32 + nt * 8 + 2 * (lane & 3);
            float bx = b2[col], by = b2[col + 1];
            float h00 = fmaxf(c[mt][nt][0] + bx, 0.f);
            float h01 = fmaxf(c[mt][nt][1] + by, 0.f);
            float h10 = fmaxf(c[mt][nt][2] + bx, 0.f);
            float h11 = fmaxf(c[mt][nt][3] + by, 0.f);
            if (r0 < NN) *(float2*)(d_h + (size_t)r0 * HH + col) = make_float2(h00, h01);
            if (r1 < NN) *(float2*)(d_h + (size_t)r1 * HH + col) = make_float2(h10, h11);
            float wr0 = Wrel[col], wr1 = Wrel[col + 1];
            float wo0 = Wroot[col], wo1 = Wroot[col + 1];
            pr0 += h00 * wr0 + h01 * wr1;  po0 += h00 * wo0 + h01 * wo1;
            pr1 += h10 * wr0 + h11 * wr1;  po1 += h10 * wo0 + h11 * wo1;
        }
        pr0 += __shfl_xor_sync(0xffffffffu, pr0, 1);
        pr0 += __shfl_xor_sync(0xffffffffu, pr0, 2);
        po0 += __shfl_xor_sync(0xffffffffu, po0, 1);
        po0 += __shfl_xor_sync(0xffffffffu, po0, 2);
        pr1 += __shfl_xor_sync(0xffffffffu, pr1, 1);
        pr1 += __shfl_xor_sync(0xffffffffu, pr1, 2);
        po1 += __shfl_xor_sync(0xffffffffu, po1, 1);
        po1 += __shfl_xor_sync(0xffffffffu, po1, 2);
        if ((lane & 3) == 0) {
            if (r0 < NN) { atomicAdd(&d_r[r0], pr0); atomicAdd(&d_root[r0], po0); }
            if (r1 < NN) { atomicAdd(&d_r[r1], pr1); atomicAdd(&d_root[r1], po1); }
        }
    }
}

// ---------------- score: brel + root + sum_{edges} r[src] ----------------
__global__ void k_score(const float* __restrict__ brel) {
    int i = blockIdx.x * blockDim.x + threadIdx.x;
    if (i >= NN) return;
    float sc = brel[0] + d_root[i];
    int beg = d_rowptr[i], end = d_rowptr[i + 1];
    for (int e = beg; e < end; e++) sc += d_r[d_col[e]];
    d_score[i] = sc;
}

// ---------------- per-graph top-K (bitonic sort) + tanh-gated global max pool ----------------
__global__ __launch_bounds__(512) void k_pool(float* __restrict__ out) {
    __shared__ float ss[1024];
    __shared__ int   si[1024];
    __shared__ float red[512];
    int b = blockIdx.x, t = threadIdx.x;
    for (int i = t; i < 1024; i += 512) {
        if (i < NPGc) { ss[i] = d_score[b * NPGc + i]; si[i] = i; }
        else          { ss[i] = -INFINITY;             si[i] = 0x7fffffff; }
    }
    __syncthreads();
    // sort descending by score, ascending index on ties (matches top_k stability)
    for (int k = 2; k <= 1024; k <<= 1) {
        for (int j = k >> 1; j > 0; j >>= 1) {
            #pragma unroll
            for (int half = 0; half < 2; half++) {
                int i = t + half * 512;
                int ixj = i ^ j;
                if (ixj > i) {
                    float s1 = ss[i], s2 = ss[ixj];
                    int   i1 = si[i], i2 = si[ixj];
                    bool up  = ((i & k) == 0);
                    bool b21 = (s2 > s1) || (s2 == s1 && i2 < i1);
                    bool b12 = (s1 > s2) || (s1 == s2 && i1 < i2);
                    if (up ? b21 : b12) {
                        ss[i] = s2; ss[ixj] = s1;
                        si[i] = i2; si[ixj] = i1;
                    }
                }
            }
            __syncthreads();
        }
    }
    for (int i = t; i < KSEL; i += 512) ss[i] = tanhf(ss[i]);
    __syncthreads();
    int part = t >> 8, f = t & 255;
    float m = -INFINITY;
    int j0 = part * (KSEL / 2), j1 = j0 + (KSEL / 2);
    for (int j = j0; j < j1; j++) {
        int node = b * NPGc + si[j];
        m = fmaxf(m, d_h[(size_t)node * HH + f] * ss[j]);
    }
    red[t] = m;
    __syncthreads();
    if (part == 0) out[b * HH + f] = fmaxf(red[t], red[t + 256]);
}

// ---------------- launch ----------------
extern "C" void kernel_launch(void* const* d_in, const int* in_sizes, int n_in,
                              void* d_out, int out_size) {
    const int*   x     = (const int*)d_in[0];
    const int*   ei    = (const int*)d_in[1];
    const float* W1    = (const float*)d_in[3];
    const float* b1    = (const float*)d_in[4];
    const float* W2    = (const float*)d_in[5];
    const float* b2    = (const float*)d_in[6];
    const float* Wrel  = (const float*)d_in[7];
    const float* brel  = (const float*)d_in[8];
    const float* Wroot = (const float*)d_in[9];
    float* out = (float*)d_out;
    const int* src = ei;
    const int* dst = ei + EE;

    k_zero   <<<(NN + 255) / 256, 256>>>();
    k_hist   <<<(EE + 255) / 256, 256>>>(dst);
    k_scan   <<<1, 1024>>>();
    k_scatter<<<(EE + 255) / 256, 256>>>(src, dst);
    k_layer1 <<<(NN + 7) / 8, 256>>>(x, W1, b1);
    k_agg    <<<(NN + 7) / 8, 256>>>();
    k_gemm   <<<dim3((NN + BM - 1) / BM, HH / BN), 256>>>(W2, b2, Wrel, Wroot);
    k_score  <<<(NN + 255) / 256, 256>>>(brel);
    k_pool   <<<BB, 512>>>(out);
}

// round 5
// speedup vs baseline: 1.7209x; 1.7209x over previous
#include <cuda_runtime.h>
#include <math.h>
#include <stdint.h>

#define NN   50000
#define BB   50
#define NPGc 1000
#define EE   300000
#define HH   256
#define KSEL 500
#define SCB  196           // ceil(NN/256) scan blocks

// ---------------- scratch (static device globals; no allocation) ----------------
__device__ float d_h1[NN * HH];      // layer1 output
__device__ float d_g [NN * HH];      // aggregated h1, tf32 bits, paired-k layout
__device__ float d_h [NN * HH];      // layer2 output (linear layout)
__device__ float d_w2t[HH * HH];     // W2^T [n][k], tf32 bits, paired-k layout
__device__ int   d_indeg[NN];
__device__ int   d_rowptr[NN + 1];
__device__ int   d_fill[NN];
__device__ int   d_col[EE];
__device__ float d_dinv[NN];
__device__ float d_r[NN];
__device__ float d_root[NN];
__device__ float d_score[NN];
__device__ int   d_bsum[SCB];
__device__ int   d_boff[SCB];

// ---------------- helpers ----------------
__device__ __forceinline__ unsigned tf32r(float f) {
    unsigned u;
    asm("cvt.rna.tf32.f32 %0, %1;" : "=r"(u) : "f"(f));
    return u;
}
__device__ __forceinline__ uint32_t smem_u32(const void* p) {
    uint32_t a;
    asm("{ .reg .u64 t; cvta.to.shared.u64 t, %1; cvt.u32.u64 %0, t; }" : "=r"(a) : "l"(p));
    return a;
}
__device__ __forceinline__ void cpa16(uint32_t dst, const void* src, int srcsz) {
    asm volatile("cp.async.ca.shared.global [%0], [%1], 16, %2;"
                 :: "r"(dst), "l"(src), "r"(srcsz));
}
#define CPA_COMMIT() asm volatile("cp.async.commit_group;" ::: "memory")
#define CPA_WAIT(n)  asm volatile("cp.async.wait_group %0;" :: "n"(n) : "memory")

// ---------------- init + histogram ----------------
__global__ void k_zero() {
    int i = blockIdx.x * blockDim.x + threadIdx.x;
    if (i < NN) { d_indeg[i] = 0; d_fill[i] = 0; d_r[i] = 0.f; d_root[i] = 0.f; }
}
__global__ void k_hist(const int* __restrict__ dst) {
    int i = blockIdx.x * blockDim.x + threadIdx.x;
    if (i < EE) atomicAdd(&d_indeg[dst[i]], 1);
}

// ---------------- multi-block exclusive scan of d_indeg -> d_rowptr ----------------
__global__ __launch_bounds__(256) void k_scan1() {
    __shared__ int ws[8];
    int t = threadIdx.x, lane = t & 31, wid = t >> 5;
    int i = blockIdx.x * 256 + t;
    int v = (i < NN) ? d_indeg[i] : 0;
    int s = v;
    #pragma unroll
    for (int o = 16; o > 0; o >>= 1) s += __shfl_down_sync(0xffffffffu, s, o);
    if (lane == 0) ws[wid] = s;
    __syncthreads();
    if (t < 8) {
        int x = ws[t];
        #pragma unroll
        for (int o = 4; o > 0; o >>= 1) x += __shfl_down_sync(0xffu, x, o);
        if (t == 0) d_bsum[blockIdx.x] = x;
    }
}
__global__ __launch_bounds__(256) void k_scan2() {
    __shared__ int ws[8];
    int t = threadIdx.x, lane = t & 31, wid = t >> 5;
    int v = (t < SCB) ? d_bsum[t] : 0;
    int s = v;
    #pragma unroll
    for (int o = 1; o < 32; o <<= 1) {
        int n = __shfl_up_sync(0xffffffffu, s, o);
        if (lane >= o) s += n;
    }
    if (lane == 31) ws[wid] = s;
    __syncthreads();
    if (wid == 0 && lane < 8) {
        int x = ws[lane];
        #pragma unroll
        for (int o = 1; o < 8; o <<= 1) {
            int n = __shfl_up_sync(0xffu, x, o);
            if (lane >= o) x += n;
        }
        ws[lane] = x;
    }
    __syncthreads();
    int excl = s - v + (wid > 0 ? ws[wid - 1] : 0);
    if (t < SCB) d_boff[t] = excl;
    if (t == 0) d_rowptr[NN] = EE;
}
__global__ __launch_bounds__(256) void k_scan3() {
    __shared__ int ws[8];
    int t = threadIdx.x, lane = t & 31, wid = t >> 5;
    int i = blockIdx.x * 256 + t;
    int v = (i < NN) ? d_indeg[i] : 0;
    int s = v;
    #pragma unroll
    for (int o = 1; o < 32; o <<= 1) {
        int n = __shfl_up_sync(0xffffffffu, s, o);
        if (lane >= o) s += n;
    }
    if (lane == 31) ws[wid] = s;
    __syncthreads();
    if (wid == 0 && lane < 8) {
        int x = ws[lane];
        #pragma unroll
        for (int o = 1; o < 8; o <<= 1) {
            int n = __shfl_up_sync(0xffu, x, o);
            if (lane >= o) x += n;
        }
        ws[lane] = x;
    }
    __syncthreads();
    int excl = s - v + (wid > 0 ? ws[wid - 1] : 0);
    if (i < NN) {
        d_rowptr[i] = d_boff[blockIdx.x] + excl;
        d_dinv[i]   = rsqrtf((float)(v + 1));
    }
}

__global__ void k_scatter(const int* __restrict__ src, const int* __restrict__ dst) {
    int i = blockIdx.x * blockDim.x + threadIdx.x;
    if (i < EE) {
        int d = dst[i];
        int p = d_rowptr[d] + atomicAdd(&d_fill[d], 1);
        d_col[p] = src[i];
    }
}

// ---------------- W2 transpose + tf32 + paired-k layout ----------------
// paired position within each 8-k group: p = (k&3)*2 + ((k>>2)&1)
__global__ void k_w2t(const float* __restrict__ W2) {
    int n = blockIdx.x, k = threadIdx.x;
    int p = (k & ~7) | (((k & 3) << 1) | ((k >> 2) & 1));
    d_w2t[n * HH + p] = __uint_as_float(tf32r(W2[k * HH + n]));
}

// ---------------- layer 1: fused onehot-gather GCN conv (warp per node) ----------------
__global__ __launch_bounds__(256) void k_layer1(const int* __restrict__ x,
                                                const float* __restrict__ W1,
                                                const float* __restrict__ b1) {
    int node = (blockIdx.x * blockDim.x + threadIdx.x) >> 5;
    int lane = threadIdx.x & 31;
    if (node >= NN) return;
    float dd = d_dinv[node];
    float4 a0, a1;
    {
        const float4* p = (const float4*)(W1 + (size_t)x[node] * HH) + lane * 2;
        float4 v0 = p[0], v1 = p[1];
        a0.x = dd * v0.x; a0.y = dd * v0.y; a0.z = dd * v0.z; a0.w = dd * v0.w;
        a1.x = dd * v1.x; a1.y = dd * v1.y; a1.z = dd * v1.z; a1.w = dd * v1.w;
    }
    int beg = d_rowptr[node], end = d_rowptr[node + 1];
    for (int e = beg; e < end; e++) {
        int s = d_col[e];
        float w = d_dinv[s];
        const float4* p = (const float4*)(W1 + (size_t)x[s] * HH) + lane * 2;
        float4 v0 = p[0], v1 = p[1];
        a0.x += w * v0.x; a0.y += w * v0.y; a0.z += w * v0.z; a0.w += w * v0.w;
        a1.x += w * v1.x; a1.y += w * v1.y; a1.z += w * v1.z; a1.w += w * v1.w;
    }
    const float4* b4 = (const float4*)b1 + lane * 2;
    float4 c0 = b4[0], c1 = b4[1];
    float4 o0, o1;
    o0.x = fmaxf(dd * a0.x + c0.x, 0.f); o0.y = fmaxf(dd * a0.y + c0.y, 0.f);
    o0.z = fmaxf(dd * a0.z + c0.z, 0.f); o0.w = fmaxf(dd * a0.w + c0.w, 0.f);
    o1.x = fmaxf(dd * a1.x + c1.x, 0.f); o1.y = fmaxf(dd * a1.y + c1.y, 0.f);
    o1.z = fmaxf(dd * a1.z + c1.z, 0.f); o1.w = fmaxf(dd * a1.w + c1.w, 0.f);
    float4* outp = (float4*)(d_h1 + (size_t)node * HH) + lane * 2;
    outp[0] = o0; outp[1] = o1;
}

// ---------------- layer 2 aggregation: tf32 bits, paired-k interleaved output ----------------
__global__ __launch_bounds__(256) void k_agg() {
    int node = (blockIdx.x * blockDim.x + threadIdx.x) >> 5;
    int lane = threadIdx.x & 31;
    if (node >= NN) return;
    float dd = d_dinv[node];
    float4 a0, a1;
    {
        const float4* p = (const float4*)(d_h1 + (size_t)node * HH) + lane * 2;
        float4 v0 = p[0], v1 = p[1];
        a0.x = dd * v0.x; a0.y = dd * v0.y; a0.z = dd * v0.z; a0.w = dd * v0.w;
        a1.x = dd * v1.x; a1.y = dd * v1.y; a1.z = dd * v1.z; a1.w = dd * v1.w;
    }
    int beg = d_rowptr[node], end = d_rowptr[node + 1];
    for (int e = beg; e < end; e++) {
        int s = d_col[e];
        float w = d_dinv[s];
        const float4* p = (const float4*)(d_h1 + (size_t)s * HH) + lane * 2;
        float4 v0 = p[0], v1 = p[1];
        a0.x += w * v0.x; a0.y += w * v0.y; a0.z += w * v0.z; a0.w += w * v0.w;
        a1.x += w * v1.x; a1.y += w * v1.y; a1.z += w * v1.z; a1.w += w * v1.w;
    }
    // lane owns k in [8*lane, 8*lane+8): k0..k3 = a0.xyzw, k4..k7 = a1.xyzw
    // paired layout: [k0,k4,k1,k5,k2,k6,k3,k7]
    float4 o0, o1;
    o0.x = __uint_as_float(tf32r(dd * a0.x)); o0.y = __uint_as_float(tf32r(dd * a1.x));
    o0.z = __uint_as_float(tf32r(dd * a0.y)); o0.w = __uint_as_float(tf32r(dd * a1.y));
    o1.x = __uint_as_float(tf32r(dd * a0.z)); o1.y = __uint_as_float(tf32r(dd * a1.z));
    o1.z = __uint_as_float(tf32r(dd * a0.w)); o1.w = __uint_as_float(tf32r(dd * a1.w));
    float4* outp = (float4*)(d_g + (size_t)node * HH) + lane * 2;
    outp[0] = o0; outp[1] = o1;
}

// ---------------- GEMM: h = relu(g @ W2 + b2) via mma.sync tf32, fused scorer ----------------
// 128x128 tile, BK=16, cp.async double-buffered, paired-k smem (LDS.64 fragments).
// smem row stride 24 floats -> conflict-free 64-bit LDS across both phases.
#define SROW 24
#define STG  (128 * SROW)         // floats per stage per array (3072)
#define GEMM_SMEM ((4 * STG + 3 * HH) * 4)

__global__ __launch_bounds__(256) void k_gemm(const float* __restrict__ b2,
                                              const float* __restrict__ Wrel,
                                              const float* __restrict__ Wroot) {
    extern __shared__ __align__(16) float sm[];
    float* sA  = sm;               // 2 stages x 128 x 24
    float* sB  = sm + 2 * STG;     // 2 stages x 128 x 24
    float* b2s = sm + 4 * STG;     // full HH
    float* wrs = b2s + HH;
    float* wos = wrs + HH;
    uint32_t sA_u = smem_u32(sA), sB_u = smem_u32(sB);

    int tid = threadIdx.x, lane = tid & 31, warpId = tid >> 5;
    int warp_m = warpId & 1, warp_n = warpId >> 1;
    int rowBase = blockIdx.x * 128;
    int colBase = blockIdx.y * 128;

    for (int i = tid; i < HH; i += 256) { b2s[i] = b2[i]; wrs[i] = Wrel[i]; wos[i] = Wroot[i]; }

    float c[4][4][4];
    #pragma unroll
    for (int mt = 0; mt < 4; mt++)
        #pragma unroll
        for (int nt = 0; nt < 4; nt++)
            #pragma unroll
            for (int q = 0; q < 4; q++) c[mt][nt][q] = 0.f;

    int cr = tid >> 2, cq = tid & 3;    // copy row/quad (rows cr, cr+64)
    #define PREFETCH(s) do {                                                        \
        int buf = (s) & 1;                                                          \
        _Pragma("unroll")                                                           \
        for (int h = 0; h < 2; h++) {                                               \
            int row = cr + h * 64;                                                  \
            int gr = rowBase + row;                                                 \
            int sz = (gr < NN) ? 16 : 0;                                            \
            int grc = (gr < NN) ? gr : 0;                                           \
            cpa16(sA_u + (uint32_t)(buf * STG + row * SROW + cq * 4) * 4,           \
                  d_g + (size_t)grc * HH + (s) * 16 + cq * 4, sz);                  \
            int nrow = colBase + row;                                               \
            cpa16(sB_u + (uint32_t)(buf * STG + row * SROW + cq * 4) * 4,           \
                  d_w2t + (size_t)nrow * HH + (s) * 16 + cq * 4, 16);               \
        }                                                                           \
    } while (0)

    PREFETCH(0); CPA_COMMIT();

    int fc = lane & 3, fr = lane >> 2;
    for (int s = 0; s < 16; s++) {
        if (s < 15) { PREFETCH(s + 1); CPA_COMMIT(); CPA_WAIT(1); }
        else        { CPA_WAIT(0); }
        __syncthreads();
        const float* A = sA + (s & 1) * STG;
        const float* B = sB + (s & 1) * STG;
        #pragma unroll
        for (int ks = 0; ks < 2; ks++) {
            int ko = ks * 8 + 2 * fc;
            float2 alo[4], ahi[4], bf[4];
            #pragma unroll
            for (int mt = 0; mt < 4; mt++) {
                int mr = warp_m * 64 + mt * 16 + fr;
                alo[mt] = *(const float2*)(A + mr * SROW + ko);
                ahi[mt] = *(const float2*)(A + (mr + 8) * SROW + ko);
            }
            #pragma unroll
            for (int nt = 0; nt < 4; nt++) {
                int nr = warp_n * 32 + nt * 8 + fr;
                bf[nt] = *(const float2*)(B + nr * SROW + ko);
            }
            #pragma unroll
            for (int mt = 0; mt < 4; mt++)
                #pragma unroll
                for (int nt = 0; nt < 4; nt++) {
                    asm volatile(
                        "mma.sync.aligned.m16n8k8.row.col.f32.tf32.tf32.f32 "
                        "{%0,%1,%2,%3}, {%4,%5,%6,%7}, {%8,%9}, {%0,%1,%2,%3};"
                        : "+f"(c[mt][nt][0]), "+f"(c[mt][nt][1]),
                          "+f"(c[mt][nt][2]), "+f"(c[mt][nt][3])
                        : "r"(__float_as_uint(alo[mt].x)), "r"(__float_as_uint(ahi[mt].x)),
                          "r"(__float_as_uint(alo[mt].y)), "r"(__float_as_uint(ahi[mt].y)),
                          "r"(__float_as_uint(bf[nt].x)),  "r"(__float_as_uint(bf[nt].y)));
                }
        }
        __syncthreads();
    }

    // epilogue: bias + relu + store h, fused r/root partial dot products
    #pragma unroll
    for (int mt = 0; mt < 4; mt++) {
        int r0 = rowBase + warp_m * 64 + mt * 16 + (lane >> 2);
        int r1 = r0 + 8;
        float pr0 = 0.f, po0 = 0.f, pr1 = 0.f, po1 = 0.f;
        #pragma unroll
        for (int nt = 0; nt < 4; nt++) {
            int col = colBase + warp_n * 32 + nt * 8 + 2 * (lane & 3);
            float bx = b2s[col], by = b2s[col + 1];
            float h00 = fmaxf(c[mt][nt][0] + bx, 0.f);
            float h01 = fmaxf(c[mt][nt][1] + by, 0.f);
            float h10 = fmaxf(c[mt][nt][2] + bx, 0.f);
            float h11 = fmaxf(c[mt][nt][3] + by, 0.f);
            if (r0 < NN) *(float2*)(d_h + (size_t)r0 * HH + col) = make_float2(h00, h01);
            if (r1 < NN) *(float2*)(d_h + (size_t)r1 * HH + col) = make_float2(h10, h11);
            float wr0 = wrs[col], wr1 = wrs[col + 1];
            float wo0 = wos[col], wo1 = wos[col + 1];
            pr0 += h00 * wr0 + h01 * wr1;  po0 += h00 * wo0 + h01 * wo1;
            pr1 += h10 * wr0 + h11 * wr1;  po1 += h10 * wo0 + h11 * wo1;
        }
        pr0 += __shfl_xor_sync(0xffffffffu, pr0, 1);
        pr0 += __shfl_xor_sync(0xffffffffu, pr0, 2);
        po0 += __shfl_xor_sync(0xffffffffu, po0, 1);
        po0 += __shfl_xor_sync(0xffffffffu, po0, 2);
        pr1 += __shfl_xor_sync(0xffffffffu, pr1, 1);
        pr1 += __shfl_xor_sync(0xffffffffu, pr1, 2);
        po1 += __shfl_xor_sync(0xffffffffu, po1, 1);
        po1 += __shfl_xor_sync(0xffffffffu, po1, 2);
        if ((lane & 3) == 0) {
            if (r0 < NN) { atomicAdd(&d_r[r0], pr0); atomicAdd(&d_root[r0], po0); }
            if (r1 < NN) { atomicAdd(&d_r[r1], pr1); atomicAdd(&d_root[r1], po1); }
        }
    }
}

// ---------------- score: brel + root + sum_{edges} r[src] ----------------
__global__ void k_score(const float* __restrict__ brel) {
    int i = blockIdx.x * blockDim.x + threadIdx.x;
    if (i >= NN) return;
    float sc = brel[0] + d_root[i];
    int beg = d_rowptr[i], end = d_rowptr[i + 1];
    for (int e = beg; e < end; e++) sc += d_r[d_col[e]];
    d_score[i] = sc;
}

// ---------------- per-graph top-K (bitonic) + tanh-gated global max pool ----------------
__global__ __launch_bounds__(512) void k_pool(float* __restrict__ out) {
    __shared__ float ss[1024];
    __shared__ int   si[1024];
    __shared__ float red[512];
    int b = blockIdx.x, t = threadIdx.x;
    for (int i = t; i < 1024; i += 512) {
        if (i < NPGc) { ss[i] = d_score[b * NPGc + i]; si[i] = i; }
        else          { ss[i] = -INFINITY;             si[i] = 0x7fffffff; }
    }
    __syncthreads();
    for (int k = 2; k <= 1024; k <<= 1) {
        for (int j = k >> 1; j > 0; j >>= 1) {
            #pragma unroll
            for (int half = 0; half < 2; half++) {
                int i = t + half * 512;
                int ixj = i ^ j;
                if (ixj > i) {
                    float s1 = ss[i], s2 = ss[ixj];
                    int   i1 = si[i], i2 = si[ixj];
                    bool up  = ((i & k) == 0);
                    bool b21 = (s2 > s1) || (s2 == s1 && i2 < i1);
                    bool b12 = (s1 > s2) || (s1 == s2 && i1 < i2);
                    if (up ? b21 : b12) {
                        ss[i] = s2; ss[ixj] = s1;
                        si[i] = i2; si[ixj] = i1;
                    }
                }
            }
            __syncthreads();
        }
    }
    for (int i = t; i < KSEL; i += 512) ss[i] = tanhf(ss[i]);
    __syncthreads();
    int part = t >> 8, f = t & 255;
    float m = -INFINITY;
    int j0 = part * (KSEL / 2), j1 = j0 + (KSEL / 2);
    for (int j = j0; j < j1; j++) {
        int node = b * NPGc + si[j];
        m = fmaxf(m, d_h[(size_t)node * HH + f] * ss[j]);
    }
    red[t] = m;
    __syncthreads();
    if (part == 0) out[b * HH + f] = fmaxf(red[t], red[t + 256]);
}

// ---------------- launch ----------------
extern "C" void kernel_launch(void* const* d_in, const int* in_sizes, int n_in,
                              void* d_out, int out_size) {
    const int*   x     = (const int*)d_in[0];
    const int*   ei    = (const int*)d_in[1];
    const float* W1    = (const float*)d_in[3];
    const float* b1    = (const float*)d_in[4];
    const float* W2    = (const float*)d_in[5];
    const float* b2    = (const float*)d_in[6];
    const float* Wrel  = (const float*)d_in[7];
    const float* brel  = (const float*)d_in[8];
    const float* Wroot = (const float*)d_in[9];
    float* out = (float*)d_out;
    const int* src = ei;
    const int* dst = ei + EE;

    cudaFuncSetAttribute(k_gemm, cudaFuncAttributeMaxDynamicSharedMemorySize, GEMM_SMEM);

    k_zero   <<<(NN + 255) / 256, 256>>>();
    k_hist   <<<(EE + 255) / 256, 256>>>(dst);
    k_w2t    <<<HH, HH>>>(W2);
    k_scan1  <<<SCB, 256>>>();
    k_scan2  <<<1, 256>>>();
    k_scan3  <<<SCB, 256>>>();
    k_scatter<<<(EE + 255) / 256, 256>>>(src, dst);
    k_layer1 <<<(NN + 7) / 8, 256>>>(x, W1, b1);
    k_agg    <<<(NN + 7) / 8, 256>>>();
    k_gemm   <<<dim3((NN + 127) / 128, 2), 256, GEMM_SMEM>>>(b2, Wrel, Wroot);
    k_score  <<<(NN + 255) / 256, 256>>>(brel);
    k_pool   <<<BB, 512>>>(out);
}

// round 6
// speedup vs baseline: 2.2164x; 1.2879x over previous
#include <cuda_runtime.h>
#include <cuda_fp16.h>
#include <math.h>
#include <stdint.h>

#define NN   50000
#define BB   50
#define NPGc 1000
#define EE   300000
#define HH   256
#define KSEL 500
#define SCB  196           // ceil(NN/256) scan blocks

// ---------------- scratch (static device globals; no allocation) ----------------
__device__ __half d_h1h[NN * HH];    // layer1 output, fp16
__device__ __half d_gh [NN * HH];    // aggregated h1, fp16 (GEMM A)
__device__ __half d_w2t[HH * HH];    // W2^T [n][k], fp16 (GEMM B)
__device__ float  d_h  [NN * HH];    // layer2 output, fp32
__device__ int    d_indeg[NN];
__device__ int    d_rowptr[NN + 1];
__device__ int    d_fill[NN];
__device__ int    d_col[EE];
__device__ float  d_dinv[NN];
__device__ float  d_r[NN];
__device__ float  d_root[NN];
__device__ float  d_score[NN];
__device__ int    d_bsum[SCB];
__device__ int    d_boff[SCB];

// ---------------- helpers ----------------
__device__ __forceinline__ uint32_t smem_u32(const void* p) {
    uint32_t a;
    asm("{ .reg .u64 t; cvta.to.shared.u64 t, %1; cvt.u32.u64 %0, t; }" : "=r"(a) : "l"(p));
    return a;
}
__device__ __forceinline__ void cpa16(uint32_t dst, const void* src, int srcsz) {
    asm volatile("cp.async.ca.shared.global [%0], [%1], 16, %2;"
                 :: "r"(dst), "l"(src), "r"(srcsz));
}
#define CPA_COMMIT() asm volatile("cp.async.commit_group;" ::: "memory")
#define CPA_WAIT(n)  asm volatile("cp.async.wait_group %0;" :: "n"(n) : "memory")

// ---------------- init + histogram ----------------
__global__ void k_zero() {
    int i = blockIdx.x * blockDim.x + threadIdx.x;
    if (i < NN) { d_indeg[i] = 0; d_fill[i] = 0; d_r[i] = 0.f; d_root[i] = 0.f; }
}
__global__ void k_hist(const int* __restrict__ dst) {
    int i = blockIdx.x * blockDim.x + threadIdx.x;
    if (i < EE) atomicAdd(&d_indeg[dst[i]], 1);
}

// ---------------- multi-block exclusive scan of d_indeg -> d_rowptr ----------------
__global__ __launch_bounds__(256) void k_scan1() {
    __shared__ int ws[8];
    int t = threadIdx.x, lane = t & 31, wid = t >> 5;
    int i = blockIdx.x * 256 + t;
    int v = (i < NN) ? d_indeg[i] : 0;
    int s = v;
    #pragma unroll
    for (int o = 16; o > 0; o >>= 1) s += __shfl_down_sync(0xffffffffu, s, o);
    if (lane == 0) ws[wid] = s;
    __syncthreads();
    if (t < 8) {
        int x = ws[t];
        #pragma unroll
        for (int o = 4; o > 0; o >>= 1) x += __shfl_down_sync(0xffu, x, o);
        if (t == 0) d_bsum[blockIdx.x] = x;
    }
}
__global__ __launch_bounds__(256) void k_scan2() {
    __shared__ int ws[8];
    int t = threadIdx.x, lane = t & 31, wid = t >> 5;
    int v = (t < SCB) ? d_bsum[t] : 0;
    int s = v;
    #pragma unroll
    for (int o = 1; o < 32; o <<= 1) {
        int n = __shfl_up_sync(0xffffffffu, s, o);
        if (lane >= o) s += n;
    }
    if (lane == 31) ws[wid] = s;
    __syncthreads();
    if (wid == 0 && lane < 8) {
        int x = ws[lane];
        #pragma unroll
        for (int o = 1; o < 8; o <<= 1) {
            int n = __shfl_up_sync(0xffu, x, o);
            if (lane >= o) x += n;
        }
        ws[lane] = x;
    }
    __syncthreads();
    int excl = s - v + (wid > 0 ? ws[wid - 1] : 0);
    if (t < SCB) d_boff[t] = excl;
    if (t == 0) d_rowptr[NN] = EE;
}
__global__ __launch_bounds__(256) void k_scan3() {
    __shared__ int ws[8];
    int t = threadIdx.x, lane = t & 31, wid = t >> 5;
    int i = blockIdx.x * 256 + t;
    int v = (i < NN) ? d_indeg[i] : 0;
    int s = v;
    #pragma unroll
    for (int o = 1; o < 32; o <<= 1) {
        int n = __shfl_up_sync(0xffffffffu, s, o);
        if (lane >= o) s += n;
    }
    if (lane == 31) ws[wid] = s;
    __syncthreads();
    if (wid == 0 && lane < 8) {
        int x = ws[lane];
        #pragma unroll
        for (int o = 1; o < 8; o <<= 1) {
            int n = __shfl_up_sync(0xffu, x, o);
            if (lane >= o) x += n;
        }
        ws[lane] = x;
    }
    __syncthreads();
    int excl = s - v + (wid > 0 ? ws[wid - 1] : 0);
    if (i < NN) {
        d_rowptr[i] = d_boff[blockIdx.x] + excl;
        d_dinv[i]   = rsqrtf((float)(v + 1));
    }
}

__global__ void k_scatter(const int* __restrict__ src, const int* __restrict__ dst) {
    int i = blockIdx.x * blockDim.x + threadIdx.x;
    if (i < EE) {
        int d = dst[i];
        int p = d_rowptr[d] + atomicAdd(&d_fill[d], 1);
        d_col[p] = src[i];
    }
}

// ---------------- W2 transpose -> fp16 ----------------
__global__ void k_w2t(const float* __restrict__ W2) {
    int n = blockIdx.x, k = threadIdx.x;
    d_w2t[n * HH + k] = __float2half_rn(W2[k * HH + n]);
}

// ---------------- layer 1: onehot-gather GCN conv, lane-parallel edge prefetch ----------------
__global__ __launch_bounds__(256) void k_layer1(const int* __restrict__ x,
                                                const float* __restrict__ W1,
                                                const float* __restrict__ b1) {
    int node = (blockIdx.x * blockDim.x + threadIdx.x) >> 5;
    int lane = threadIdx.x & 31;
    if (node >= NN) return;
    float dd = d_dinv[node];
    float a[8];
    {
        const float4* p = (const float4*)(W1 + (size_t)x[node] * HH) + lane * 2;
        float4 v0 = p[0], v1 = p[1];
        a[0] = dd * v0.x; a[1] = dd * v0.y; a[2] = dd * v0.z; a[3] = dd * v0.w;
        a[4] = dd * v1.x; a[5] = dd * v1.y; a[6] = dd * v1.z; a[7] = dd * v1.w;
    }
    int beg = d_rowptr[node], end = d_rowptr[node + 1];
    for (int eb = beg; eb < end; eb += 32) {
        int n = min(32, end - eb);
        int si = 0, xi = 0; float wi = 0.f;
        if (lane < n) { si = d_col[eb + lane]; wi = d_dinv[si]; xi = x[si]; }
        for (int e = 0; e < n; e++) {
            int   xe = __shfl_sync(0xffffffffu, xi, e);
            float we = __shfl_sync(0xffffffffu, wi, e);
            const float4* p = (const float4*)(W1 + (size_t)xe * HH) + lane * 2;
            float4 v0 = p[0], v1 = p[1];
            a[0] += we * v0.x; a[1] += we * v0.y; a[2] += we * v0.z; a[3] += we * v0.w;
            a[4] += we * v1.x; a[5] += we * v1.y; a[6] += we * v1.z; a[7] += we * v1.w;
        }
    }
    const float4* b4 = (const float4*)b1 + lane * 2;
    float4 c0 = b4[0], c1 = b4[1];
    float o[8];
    o[0] = fmaxf(dd * a[0] + c0.x, 0.f); o[1] = fmaxf(dd * a[1] + c0.y, 0.f);
    o[2] = fmaxf(dd * a[2] + c0.z, 0.f); o[3] = fmaxf(dd * a[3] + c0.w, 0.f);
    o[4] = fmaxf(dd * a[4] + c1.x, 0.f); o[5] = fmaxf(dd * a[5] + c1.y, 0.f);
    o[6] = fmaxf(dd * a[6] + c1.z, 0.f); o[7] = fmaxf(dd * a[7] + c1.w, 0.f);
    uint4 pk;
    ((__half2*)&pk)[0] = __floats2half2_rn(o[0], o[1]);
    ((__half2*)&pk)[1] = __floats2half2_rn(o[2], o[3]);
    ((__half2*)&pk)[2] = __floats2half2_rn(o[4], o[5]);
    ((__half2*)&pk)[3] = __floats2half2_rn(o[6], o[7]);
    ((uint4*)(d_h1h + (size_t)node * HH))[lane] = pk;
}

// ---------------- layer 2 aggregation (A-hat * h1), fp16 in/out ----------------
__global__ __launch_bounds__(256) void k_agg() {
    int node = (blockIdx.x * blockDim.x + threadIdx.x) >> 5;
    int lane = threadIdx.x & 31;
    if (node >= NN) return;
    float dd = d_dinv[node];
    float a[8];
    {
        uint4 v = ((const uint4*)(d_h1h + (size_t)node * HH))[lane];
        #pragma unroll
        for (int j = 0; j < 4; j++) {
            float2 f = __half22float2(((__half2*)&v)[j]);
            a[2*j]   = dd * f.x;
            a[2*j+1] = dd * f.y;
        }
    }
    int beg = d_rowptr[node], end = d_rowptr[node + 1];
    for (int eb = beg; eb < end; eb += 32) {
        int n = min(32, end - eb);
        int si = 0; float wi = 0.f;
        if (lane < n) { si = d_col[eb + lane]; wi = d_dinv[si]; }
        for (int e = 0; e < n; e++) {
            int   se = __shfl_sync(0xffffffffu, si, e);
            float we = __shfl_sync(0xffffffffu, wi, e);
            uint4 v = ((const uint4*)(d_h1h + (size_t)se * HH))[lane];
            #pragma unroll
            for (int j = 0; j < 4; j++) {
                float2 f = __half22float2(((__half2*)&v)[j]);
                a[2*j]   += we * f.x;
                a[2*j+1] += we * f.y;
            }
        }
    }
    uint4 pk;
    #pragma unroll
    for (int j = 0; j < 4; j++)
        ((__half2*)&pk)[j] = __floats2half2_rn(dd * a[2*j], dd * a[2*j+1]);
    ((uint4*)(d_gh + (size_t)node * HH))[lane] = pk;
}

// ---------------- GEMM: h = relu(g @ W2 + b2) via fp16 mma m16n8k16, fused scorer ----------------
// 128x128 tile, BK=32 halves, cp.async double-buffered.
// smem row stride 40 halves (80B) -> conflict-free LDS.32 fragments.
#define SROWH 40
#define STGH  (128 * SROWH)            // halves per stage per array (5120)
#define GEMM_SMEM (4 * STGH * 2 + 3 * HH * 4)

__global__ __launch_bounds__(256) void k_gemm(const float* __restrict__ b2,
                                              const float* __restrict__ Wrel,
                                              const float* __restrict__ Wroot) {
    extern __shared__ __align__(16) char smc[];
    __half* sA = (__half*)smc;                    // 2 stages x 128 x 40
    __half* sB = sA + 2 * STGH;                   // 2 stages x 128 x 40
    float*  b2s = (float*)(sB + 2 * STGH);        // full HH
    float*  wrs = b2s + HH;
    float*  wos = wrs + HH;
    uint32_t sA_u = smem_u32(sA), sB_u = smem_u32(sB);

    int tid = threadIdx.x, lane = tid & 31, warpId = tid >> 5;
    int warp_m = warpId & 1, warp_n = warpId >> 1;
    int rowBase = blockIdx.x * 128;
    int colBase = blockIdx.y * 128;

    for (int i = tid; i < HH; i += 256) { b2s[i] = b2[i]; wrs[i] = Wrel[i]; wos[i] = Wroot[i]; }

    float c[4][4][4];
    #pragma unroll
    for (int mt = 0; mt < 4; mt++)
        #pragma unroll
        for (int nt = 0; nt < 4; nt++)
            #pragma unroll
            for (int q = 0; q < 4; q++) c[mt][nt][q] = 0.f;

    // copy map: row = tid>>1, chunks 2*(tid&1)+{0,1}; 16B = 8 halves per chunk
    int cprow = tid >> 1, cpc = (tid & 1) * 2;
    #define PREFETCH(s) do {                                                         \
        int buf = (s) & 1;                                                           \
        int gr = rowBase + cprow;                                                    \
        int sz = (gr < NN) ? 16 : 0;                                                 \
        int grc = (gr < NN) ? gr : 0;                                                \
        int nrow = colBase + cprow;                                                  \
        _Pragma("unroll")                                                            \
        for (int h = 0; h < 2; h++) {                                                \
            int cc = cpc + h;                                                        \
            cpa16(sA_u + (uint32_t)(buf * STGH + cprow * SROWH + cc * 8) * 2,        \
                  d_gh + (size_t)grc * HH + (s) * 32 + cc * 8, sz);                  \
            cpa16(sB_u + (uint32_t)(buf * STGH + cprow * SROWH + cc * 8) * 2,        \
                  d_w2t + (size_t)nrow * HH + (s) * 32 + cc * 8, 16);                \
        }                                                                            \
    } while (0)

    PREFETCH(0); CPA_COMMIT();

    int fc = lane & 3, fr = lane >> 2;
    for (int s = 0; s < 8; s++) {
        if (s < 7) { PREFETCH(s + 1); CPA_COMMIT(); CPA_WAIT(1); }
        else       { CPA_WAIT(0); }
        __syncthreads();
        const __half* A = sA + (s & 1) * STGH;
        const __half* B = sB + (s & 1) * STGH;
        #pragma unroll
        for (int ks = 0; ks < 2; ks++) {
            uint32_t a0[4], a1[4], a2[4], a3[4], b0[4], b1[4];
            #pragma unroll
            for (int mt = 0; mt < 4; mt++) {
                int mr = warp_m * 64 + mt * 16 + fr;
                const __half* pa  = A + mr * SROWH + ks * 16 + fc * 2;
                const __half* pa8 = pa + 8 * SROWH;
                a0[mt] = *(const uint32_t*)pa;
                a2[mt] = *(const uint32_t*)(pa + 8);
                a1[mt] = *(const uint32_t*)pa8;
                a3[mt] = *(const uint32_t*)(pa8 + 8);
            }
            #pragma unroll
            for (int nt = 0; nt < 4; nt++) {
                int nr = warp_n * 32 + nt * 8 + fr;
                const __half* pb = B + nr * SROWH + ks * 16 + fc * 2;
                b0[nt] = *(const uint32_t*)pb;
                b1[nt] = *(const uint32_t*)(pb + 8);
            }
            #pragma unroll
            for (int mt = 0; mt < 4; mt++)
                #pragma unroll
                for (int nt = 0; nt < 4; nt++) {
                    asm volatile(
                        "mma.sync.aligned.m16n8k16.row.col.f32.f16.f16.f32 "
                        "{%0,%1,%2,%3}, {%4,%5,%6,%7}, {%8,%9}, {%0,%1,%2,%3};"
                        : "+f"(c[mt][nt][0]), "+f"(c[mt][nt][1]),
                          "+f"(c[mt][nt][2]), "+f"(c[mt][nt][3])
                        : "r"(a0[mt]), "r"(a1[mt]), "r"(a2[mt]), "r"(a3[mt]),
                          "r"(b0[nt]), "r"(b1[nt]));
                }
        }
        __syncthreads();
    }

    // epilogue: bias + relu + store h (fp32), fused r/root partial dot products
    #pragma unroll
    for (int mt = 0; mt < 4; mt++) {
        int r0 = rowBase + warp_m * 64 + mt * 16 + (lane >> 2);
        int r1 = r0 + 8;
        float pr0 = 0.f, po0 = 0.f, pr1 = 0.f, po1 = 0.f;
        #pragma unroll
        for (int nt = 0; nt < 4; nt++) {
            int col = colBase + warp_n * 32 + nt * 8 + 2 * (lane & 3);
            float bx = b2s[col], by = b2s[col + 1];
            float h00 = fmaxf(c[mt][nt][0] + bx, 0.f);
            float h01 = fmaxf(c[mt][nt][1] + by, 0.f);
            float h10 = fmaxf(c[mt][nt][2] + bx, 0.f);
            float h11 = fmaxf(c[mt][nt][3] + by, 0.f);
            if (r0 < NN) *(float2*)(d_h + (size_t)r0 * HH + col) = make_float2(h00, h01);
            if (r1 < NN) *(float2*)(d_h + (size_t)r1 * HH + col) = make_float2(h10, h11);
            float wr0 = wrs[col], wr1 = wrs[col + 1];
            float wo0 = wos[col], wo1 = wos[col + 1];
            pr0 += h00 * wr0 + h01 * wr1;  po0 += h00 * wo0 + h01 * wo1;
            pr1 += h10 * wr0 + h11 * wr1;  po1 += h10 * wo0 + h11 * wo1;
        }
        pr0 += __shfl_xor_sync(0xffffffffu, pr0, 1);
        pr0 += __shfl_xor_sync(0xffffffffu, pr0, 2);
        po0 += __shfl_xor_sync(0xffffffffu, po0, 1);
        po0 += __shfl_xor_sync(0xffffffffu, po0, 2);
        pr1 += __shfl_xor_sync(0xffffffffu, pr1, 1);
        pr1 += __shfl_xor_sync(0xffffffffu, pr1, 2);
        po1 += __shfl_xor_sync(0xffffffffu, po1, 1);
        po1 += __shfl_xor_sync(0xffffffffu, po1, 2);
        if ((lane & 3) == 0) {
            if (r0 < NN) { atomicAdd(&d_r[r0], pr0); atomicAdd(&d_root[r0], po0); }
            if (r1 < NN) { atomicAdd(&d_r[r1], pr1); atomicAdd(&d_root[r1], po1); }
        }
    }
}

// ---------------- score: brel + root + sum_{edges} r[src] ----------------
__global__ void k_score(const float* __restrict__ brel) {
    int i = blockIdx.x * blockDim.x + threadIdx.x;
    if (i >= NN) return;
    float sc = brel[0] + d_root[i];
    int beg = d_rowptr[i], end = d_rowptr[i + 1];
    for (int e = beg; e < end; e++) sc += d_r[d_col[e]];
    d_score[i] = sc;
}

// ---------------- per-graph top-K (bitonic) + tanh-gated global max pool ----------------
__global__ __launch_bounds__(512) void k_pool(float* __restrict__ out) {
    __shared__ float ss[1024];
    __shared__ int   si[1024];
    __shared__ float red[512];
    int b = blockIdx.x, t = threadIdx.x;
    for (int i = t; i < 1024; i += 512) {
        if (i < NPGc) { ss[i] = d_score[b * NPGc + i]; si[i] = i; }
        else          { ss[i] = -INFINITY;             si[i] = 0x7fffffff; }
    }
    __syncthreads();
    for (int k = 2; k <= 1024; k <<= 1) {
        for (int j = k >> 1; j > 0; j >>= 1) {
            #pragma unroll
            for (int half = 0; half < 2; half++) {
                int i = t + half * 512;
                int ixj = i ^ j;
                if (ixj > i) {
                    float s1 = ss[i], s2 = ss[ixj];
                    int   i1 = si[i], i2 = si[ixj];
                    bool up  = ((i & k) == 0);
                    bool b21 = (s2 > s1) || (s2 == s1 && i2 < i1);
                    bool b12 = (s1 > s2) || (s1 == s2 && i1 < i2);
                    if (up ? b21 : b12) {
                        ss[i] = s2; ss[ixj] = s1;
                        si[i] = i2; si[ixj] = i1;
                    }
                }
            }
            __syncthreads();
        }
    }
    for (int i = t; i < KSEL; i += 512) ss[i] = tanhf(ss[i]);
    __syncthreads();
    int part = t >> 8, f = t & 255;
    float m = -INFINITY;
    int j0 = part * (KSEL / 2), j1 = j0 + (KSEL / 2);
    for (int j = j0; j < j1; j++) {
        int node = b * NPGc + si[j];
        m = fmaxf(m, d_h[(size_t)node * HH + f] * ss[j]);
    }
    red[t] = m;
    __syncthreads();
    if (part == 0) out[b * HH + f] = fmaxf(red[t], red[t + 256]);
}

// ---------------- launch ----------------
extern "C" void kernel_launch(void* const* d_in, const int* in_sizes, int n_in,
                              void* d_out, int out_size) {
    const int*   x     = (const int*)d_in[0];
    const int*   ei    = (const int*)d_in[1];
    const float* W1    = (const float*)d_in[3];
    const float* b1    = (const float*)d_in[4];
    const float* W2    = (const float*)d_in[5];
    const float* b2    = (const float*)d_in[6];
    const float* Wrel  = (const float*)d_in[7];
    const float* brel  = (const float*)d_in[8];
    const float* Wroot = (const float*)d_in[9];
    float* out = (float*)d_out;
    const int* src = ei;
    const int* dst = ei + EE;

    cudaFuncSetAttribute(k_gemm, cudaFuncAttributeMaxDynamicSharedMemorySize, GEMM_SMEM);

    k_zero   <<<(NN + 255) / 256, 256>>>();
    k_hist   <<<(EE + 255) / 256, 256>>>(dst);
    k_w2t    <<<HH, HH>>>(W2);
    k_scan1  <<<SCB, 256>>>();
    k_scan2  <<<1, 256>>>();
    k_scan3  <<<SCB, 256>>>();
    k_scatter<<<(EE + 255) / 256, 256>>>(src, dst);
    k_layer1 <<<(NN + 7) / 8, 256>>>(x, W1, b1);
    k_agg    <<<(NN + 7) / 8, 256>>>();
    k_gemm   <<<dim3((NN + 127) / 128, 2), 256, GEMM_SMEM>>>(b2, Wrel, Wroot);
    k_score  <<<(NN + 255) / 256, 256>>>(brel);
    k_pool   <<<BB, 512>>>(out);
}